// round 10
// baseline (speedup 1.0000x reference)
#include <cuda_runtime.h>
#include <cuda_fp16.h>
#include <cstdint>

#define D 256
#define NMAX 65536
#define STRIDE 96          // per-dst bucket capacity (Poisson(16), P(deg>96) ~ 0)

// ---------------------------------------------------------------------------
// Scratch (__device__ globals; no cudaMalloc allowed).
// ---------------------------------------------------------------------------
__device__ __align__(16) float  g_al[NMAX];
__device__ __align__(16) float  g_ar[NMAX];
__device__ __align__(16) __half g_nh[(size_t)NMAX * D];           // fp16 node copy, 32 MB
__device__ __align__(16) int    g_cnt[NMAX];                      // bucket cursors
__device__ __align__(16) int2   g_pairs[(size_t)NMAX * STRIDE];   // (src, coef-bits), 48 MB
__device__ int g_is64;

// ---------------------------------------------------------------------------
// Kernel 1: per-node attention scalars + fp16 conversion of node,
// with counter zeroing and dtype probe fused in (saves a launch).
// One warp per row.
// ---------------------------------------------------------------------------
__global__ void alpha_convert_kernel(const float* __restrict__ node,
                                     const float* __restrict__ att_l,
                                     const float* __restrict__ att_r,
                                     const int* __restrict__ ei,
                                     int N)
{
    int gtid = blockIdx.x * blockDim.x + threadIdx.x;

    // fused init: zero bucket counters (grid 6250*256 = 1.6M threads >> NMAX)
    if (gtid < NMAX) g_cnt[gtid] = 0;
    // fused dtype probe: int64 little-endian with values < 2^31 has every
    // odd 32-bit word zero.
    if (blockIdx.x == 0 && threadIdx.x < 32) {
        int lane = threadIdx.x;
        int nz = 0;
#pragma unroll
        for (int k = 0; k < 4; k++)
            nz |= ei[1 + 2 * (lane * 4 + k)];
        unsigned any = __ballot_sync(0xffffffffu, nz != 0);
        if (lane == 0) g_is64 = (any == 0u);
    }

    int warp = gtid >> 5;
    int lane = threadIdx.x & 31;
    if (warp >= N) return;

    const float4* row = (const float4*)(node + (size_t)warp * D);
    const float4* L   = (const float4*)att_l;
    const float4* R   = (const float4*)att_r;
    __half2* hout = (__half2*)(g_nh + (size_t)warp * D);

    float sl = 0.f, sr = 0.f;
#pragma unroll
    for (int i = 0; i < 2; i++) {
        int idx = lane + 32 * i;
        float4 v = row[idx];
        float4 l = L[idx];
        float4 r = R[idx];
        sl += v.x * l.x + v.y * l.y + v.z * l.z + v.w * l.w;
        sr += v.x * r.x + v.y * r.y + v.z * r.z + v.w * r.w;
        __half2 h0 = __floats2half2_rn(v.x, v.y);
        __half2 h1 = __floats2half2_rn(v.z, v.w);
        hout[idx * 2 + 0] = h0;
        hout[idx * 2 + 1] = h1;
    }
#pragma unroll
    for (int o = 16; o; o >>= 1) {
        sl += __shfl_xor_sync(0xffffffffu, sl, o);
        sr += __shfl_xor_sync(0xffffffffu, sr, o);
    }
    if (lane == 0) { g_al[warp] = sl; g_ar[warp] = sr; }
}

// ---------------------------------------------------------------------------
// Kernel 2: scatter edges into fixed-stride buckets.
// ---------------------------------------------------------------------------
__global__ void scatter_kernel(const void* __restrict__ edge_index,
                               const float* __restrict__ edge_attr,
                               int E)
{
    int e = blockIdx.x * blockDim.x + threadIdx.x;
    if (e >= E) return;
    int s, d;
    if (g_is64) {
        const long long* p = (const long long*)edge_index;
        s = (int)p[e];
        d = (int)p[(size_t)E + e];
    } else {
        const int* p = (const int*)edge_index;
        s = p[e];
        d = p[E + e];
    }
    float coef = tanhf(g_al[s] + g_ar[d]) * edge_attr[e];
    int pos = atomicAdd(&g_cnt[d], 1);
    if (pos < STRIDE)
        g_pairs[(size_t)d * STRIDE + pos] = make_int2(s, __float_as_int(coef));
}

// ---------------------------------------------------------------------------
// Kernel 3: fp16 gather + skip + LayerNorm + ReLU, fused.
// TWO warps per dst row: each warp owns 128 features (lane -> 4 halves,
// LDG.64 per edge). Halves the per-edge dependent chain per warp and doubles
// the number of independent edge streams. Warp-pair LN reduce via smem.
// Block = 256 threads = 8 warps = 4 rows.
// ---------------------------------------------------------------------------
__global__ void __launch_bounds__(256)
gather_ln_kernel(const float* __restrict__ node0,
                 const float* __restrict__ lnw,
                 const float* __restrict__ lnb,
                 float* __restrict__ out,
                 int N)
{
    int tid  = threadIdx.x;
    int warp = tid >> 5;
    int lane = tid & 31;
    int rowb = warp >> 1;            // row within block: 0..3
    int half = warp & 1;             // feature half: 0 or 1
    int row  = blockIdx.x * 4 + rowb;

    __shared__ float s_sum[4][2];
    __shared__ float s_sq[4][2];

    bool active = (row < N);
    int r = active ? row : 0;

    int cnt = active ? g_cnt[r] : 0;
    if (cnt > STRIDE) cnt = STRIDE;
    const int2* bucket = g_pairs + (size_t)r * STRIDE;

    // This warp's 128-feature slice: features half*128 + lane*4 .. +3
    int fofs = half * 128 + lane * 4;   // in halves / floats

    float a[4] = {0.f, 0.f, 0.f, 0.f};

    int e = 0;
    for (; e + 4 <= cnt; e += 4) {
        int2 p0 = bucket[e + 0];
        int2 p1 = bucket[e + 1];
        int2 p2 = bucket[e + 2];
        int2 p3 = bucket[e + 3];
        // 4 independent LDG.64s in flight
        float2 h0 = *(const float2*)(g_nh + (size_t)p0.x * D + fofs);
        float2 h1 = *(const float2*)(g_nh + (size_t)p1.x * D + fofs);
        float2 h2 = *(const float2*)(g_nh + (size_t)p2.x * D + fofs);
        float2 h3 = *(const float2*)(g_nh + (size_t)p3.x * D + fofs);

        float c0 = __int_as_float(p0.y);
        float c1 = __int_as_float(p1.y);
        float c2 = __int_as_float(p2.y);
        float c3 = __int_as_float(p3.y);

        const __half2* q0 = (const __half2*)&h0;
        const __half2* q1 = (const __half2*)&h1;
        const __half2* q2 = (const __half2*)&h2;
        const __half2* q3 = (const __half2*)&h3;
#pragma unroll
        for (int j = 0; j < 2; j++) {
            float2 f0 = __half22float2(q0[j]);
            float2 f1 = __half22float2(q1[j]);
            float2 f2 = __half22float2(q2[j]);
            float2 f3 = __half22float2(q3[j]);
            a[2*j]   += c0 * f0.x + c1 * f1.x + c2 * f2.x + c3 * f3.x;
            a[2*j+1] += c0 * f0.y + c1 * f1.y + c2 * f2.y + c3 * f3.y;
        }
    }
    for (; e < cnt; e++) {
        int2 p = bucket[e];
        float coef = __int_as_float(p.y);
        float2 hv = *(const float2*)(g_nh + (size_t)p.x * D + fofs);
        const __half2* hp = (const __half2*)&hv;
#pragma unroll
        for (int j = 0; j < 2; j++) {
            float2 f = __half22float2(hp[j]);
            a[2*j]   += coef * f.x;
            a[2*j+1] += coef * f.y;
        }
    }

    // skip connection: + 0.1 * node_0 (this warp's 4 features)
    float4 z = *(const float4*)(node0 + (size_t)r * D + fofs);
    a[0] += 0.1f * z.x;
    a[1] += 0.1f * z.y;
    a[2] += 0.1f * z.z;
    a[3] += 0.1f * z.w;

    // warp-local partial sums over this half-row
    float sum = a[0] + a[1] + a[2] + a[3];
    float sq  = a[0]*a[0] + a[1]*a[1] + a[2]*a[2] + a[3]*a[3];
#pragma unroll
    for (int o = 16; o; o >>= 1) {
        sum += __shfl_xor_sync(0xffffffffu, sum, o);
        sq  += __shfl_xor_sync(0xffffffffu, sq, o);
    }
    if (lane == 0) { s_sum[rowb][half] = sum; s_sq[rowb][half] = sq; }
    __syncthreads();

    float tsum = s_sum[rowb][0] + s_sum[rowb][1];
    float tsq  = s_sq[rowb][0]  + s_sq[rowb][1];

    float mean = tsum * (1.0f / D);
    float var  = tsq * (1.0f / D) - mean * mean;
    float inv  = rsqrtf(var + 1e-5f);

    float4 w = *(const float4*)(lnw + fofs);
    float4 b = *(const float4*)(lnb + fofs);

    float4 rr;
    rr.x = fmaxf(0.f, (a[0] - mean) * inv * w.x + b.x);
    rr.y = fmaxf(0.f, (a[1] - mean) * inv * w.y + b.y);
    rr.z = fmaxf(0.f, (a[2] - mean) * inv * w.z + b.z);
    rr.w = fmaxf(0.f, (a[3] - mean) * inv * w.w + b.w);

    if (active)
        *(float4*)(out + (size_t)row * D + fofs) = rr;
}

extern "C" void kernel_launch(void* const* d_in, const int* in_sizes, int n_in,
                              void* d_out, int out_size)
{
    const float* node  = (const float*)d_in[0];
    const float* node0 = (const float*)d_in[1];
    const void*  eidx  = d_in[2];
    const float* eattr = (const float*)d_in[3];
    // d_in[4] = batch_ptr (unused in node-mode LayerNorm)
    const float* att_l = (const float*)d_in[5];
    const float* att_r = (const float*)d_in[6];
    const float* lnw   = (const float*)d_in[7];
    const float* lnb   = (const float*)d_in[8];
    float* out = (float*)d_out;

    int N = in_sizes[0] / D;
    int E = in_sizes[3];

    int nwb = (N + 7) / 8;                     // one warp per node, 8 warps/block
    alpha_convert_kernel<<<nwb, 256>>>(node, att_l, att_r, (const int*)eidx, N);

    int eb = (E + 255) / 256;
    scatter_kernel<<<eb, 256>>>(eidx, eattr, E);

    int gb = (N + 3) / 4;                      // 4 rows per 256-thread block
    gather_ln_kernel<<<gb, 256>>>(node0, lnw, lnb, out, N);
}